// round 1
// baseline (speedup 1.0000x reference)
#include <cuda_runtime.h>
#include <math.h>

// Problem shape (fixed): x (32, 1, 720, 1024) f32 -> out (32, 1, 512, 512) f32
// proj[v, z, d] = x[z, 0, v, d]
// out[z, y, xp] = (pi/720) * sum_v lerp(proj[v,z,:], t),  t = xs*cos + ys*sin + 511.5
// For this geometry t in [150.2, 872.8] => always in-bounds, no clamping needed.

#define NV  720
#define ND  1024
#define NZ  32
#define NX  512
#define NY  512
#define RY  16            // image rows per CTA

__device__ float g_cos[NV];
__device__ float g_sin[NV];

__global__ void init_trig_kernel() {
    int v = blockIdx.x * blockDim.x + threadIdx.x;
    if (v < NV) {
        float th = (float)v * (float)(M_PI / (double)NV);
        g_cos[v] = cosf(th);
        g_sin[v] = sinf(th);
    }
}

__global__ __launch_bounds__(512) void backproject_kernel(
    const float* __restrict__ x, float* __restrict__ out)
{
    __shared__ float row[2][ND];
    __shared__ float s_cos[NV];
    __shared__ float s_sin[NV];

    const int tid = threadIdx.x;          // image x column, 0..511
    const int z   = blockIdx.y;
    const int y0  = blockIdx.x * RY;

    // Stage trig tables into shared (visibility covered by first __syncthreads)
    for (int i = tid; i < NV; i += 512) {
        s_cos[i] = g_cos[i];
        s_sin[i] = g_sin[i];
    }

    const float xf  = (float)tid - 255.5f;
    const float yf0 = (float)y0  - 255.5f;

    float acc[RY];
#pragma unroll
    for (int r = 0; r < RY; r++) acc[r] = 0.0f;

    const float* __restrict__ base = x + (size_t)z * (NV * ND);

    // Preload view 0's detector row into registers (2 elements per thread)
    float p0 = base[tid];
    float p1 = base[tid + 512];

    for (int v = 0; v < NV; v++) {
        const int buf = v & 1;
        row[buf][tid]       = p0;
        row[buf][tid + 512] = p1;
        __syncthreads();   // single sync per view; safe with double buffering

        // Prefetch next view's row while computing this one
        if (v + 1 < NV) {
            const float* __restrict__ nxt = base + (size_t)(v + 1) * ND;
            p0 = nxt[tid];
            p1 = nxt[tid + 512];
        }

        const float c = s_cos[v];
        const float s = s_sin[v];
        float t = fmaf(xf, c, fmaf(yf0, s, 511.5f));
        const float* __restrict__ rb = row[buf];

#pragma unroll
        for (int r = 0; r < RY; r++) {
            // t > 0 always, so trunc == floor
            int   i0 = (int)t;
            float w  = t - (float)i0;
            float g0 = rb[i0];
            float g1 = rb[i0 + 1];
            acc[r] = fmaf(w, g1 - g0, acc[r] + g0);
            t += s;   // advancing one image row adds sin(theta) to t
        }
        // no trailing sync needed: next iteration writes the other buffer,
        // and passing the next sync implies everyone finished reading this one
    }

    const float scale = (float)(M_PI / (double)NV);
    float* __restrict__ o = out + ((size_t)z * NY + y0) * NX + tid;
#pragma unroll
    for (int r = 0; r < RY; r++) {
        o[(size_t)r * NX] = acc[r] * scale;
    }
}

extern "C" void kernel_launch(void* const* d_in, const int* in_sizes, int n_in,
                              void* d_out, int out_size)
{
    const float* x  = (const float*)d_in[0];
    float*       out = (float*)d_out;

    init_trig_kernel<<<(NV + 255) / 256, 256>>>();

    dim3 grid(NY / RY, NZ);   // (32, 32) = 1024 CTAs
    backproject_kernel<<<grid, 512>>>(x, out);
}